// round 2
// baseline (speedup 1.0000x reference)
#include <cuda_runtime.h>
#include <math.h>

// Problem constants
#define D    512
#define BB   64
#define TSRC 48
#define TTGT 48
#define VDE  32000
#define S    (BB * D)        // 32768 = one (B,D) state
#define M3   (TSRC * BB)     // 3072 rows

// ---------------- scratch (device globals; no allocation allowed) ------------
__device__ float g_Wcat[1536 * D];       // [Wz;Wr;Wn] rows, NT layout
__device__ float g_bcat[1536];
__device__ float g_Genc[M3 * 1536];      // precomputed x-gates (encoder layer1)
__device__ float g_Gdec[M3 * 1536];      // precomputed x-gates (decoder)
__device__ float g_h1[2 * S];            // encoder layer1 state (double buffer)
__device__ float g_h2[2 * S];            // encoder layer2 / decoder state
__device__ float g_H[TSRC * S];          // encoder outputs per step [t][b][d]
__device__ float g_hall[TTGT * S];       // decoder h per step
__device__ float g_ctx[TTGT * S];        // attention context per step
__device__ float g_out[TTGT * S];        // h + ctx@Wctx^T
__device__ float g_part[16 * S];         // split-K partials [mat*4+kc][b][d]

// ---------------------------------------------------------------------------
// Generic NT SGEMM: C[i,j] = sum_k A[i,k]*B[j,k] (+bias[j]) (+addend[i,j])
// Optional row gather on A: A row i -> E + ids[i]*K.
// BM=BN=128, BK=8, 256 threads, 8x8 per-thread microtile.
// All dims used are exact multiples (M=3072; N in {512,1536,32000}; K=512).
// ---------------------------------------------------------------------------
__global__ __launch_bounds__(256) void sgemm_nt(
    const float* __restrict__ A, const int* __restrict__ ids,
    const float* __restrict__ E, const float* __restrict__ Bm,
    const float* __restrict__ bias, const float* __restrict__ addend,
    float* __restrict__ C, int M, int N, int K)
{
    __shared__ __align__(16) float As[8][128];
    __shared__ __align__(16) float Bs[8][128];

    const int tid  = threadIdx.x;
    const int row0 = blockIdx.y * 128;
    const int col0 = blockIdx.x * 128;

    const int arow = tid >> 1;
    const int acol = (tid & 1) * 4;

    const float* Arow;
    if (ids) Arow = E + (size_t)ids[row0 + arow] * K;
    else     Arow = A + (size_t)(row0 + arow) * K;
    const float* Brow = Bm + (size_t)(col0 + arow) * K;   // same index pattern

    const int tr = tid >> 4;   // 0..15
    const int tc = tid & 15;   // 0..15

    float acc[8][8];
#pragma unroll
    for (int i = 0; i < 8; i++)
#pragma unroll
        for (int j = 0; j < 8; j++) acc[i][j] = 0.f;

    for (int k0 = 0; k0 < K; k0 += 8) {
        float4 av = *(const float4*)(Arow + k0 + acol);
        float4 bv = *(const float4*)(Brow + k0 + acol);
        As[acol + 0][arow] = av.x; As[acol + 1][arow] = av.y;
        As[acol + 2][arow] = av.z; As[acol + 3][arow] = av.w;
        Bs[acol + 0][arow] = bv.x; Bs[acol + 1][arow] = bv.y;
        Bs[acol + 2][arow] = bv.z; Bs[acol + 3][arow] = bv.w;
        __syncthreads();
#pragma unroll
        for (int k = 0; k < 8; k++) {
            float ar_[8], br_[8];
            *(float4*)&ar_[0] = *(const float4*)&As[k][tr * 8];
            *(float4*)&ar_[4] = *(const float4*)&As[k][tr * 8 + 4];
            *(float4*)&br_[0] = *(const float4*)&Bs[k][tc * 8];
            *(float4*)&br_[4] = *(const float4*)&Bs[k][tc * 8 + 4];
#pragma unroll
            for (int i = 0; i < 8; i++)
#pragma unroll
                for (int j = 0; j < 8; j++)
                    acc[i][j] += ar_[i] * br_[j];
        }
        __syncthreads();
    }

#pragma unroll
    for (int i = 0; i < 8; i++) {
        size_t r = (size_t)(row0 + tr * 8 + i);
#pragma unroll
        for (int j4 = 0; j4 < 2; j4++) {
            int cb = col0 + tc * 8 + j4 * 4;
            float4 v;
            v.x = acc[i][j4 * 4 + 0]; v.y = acc[i][j4 * 4 + 1];
            v.z = acc[i][j4 * 4 + 2]; v.w = acc[i][j4 * 4 + 3];
            if (bias) {
                v.x += bias[cb]; v.y += bias[cb + 1];
                v.z += bias[cb + 2]; v.w += bias[cb + 3];
            }
            if (addend) {
                float4 ad = *(const float4*)&addend[r * N + cb];
                v.x += ad.x; v.y += ad.y; v.z += ad.z; v.w += ad.w;
            }
            *(float4*)&C[r * N + cb] = v;
        }
    }
}

// ---------------------------------------------------------------------------
// Build concatenated gate weights [Wz;Wr;Wn] (1536 x 512) + bias vector.
// ---------------------------------------------------------------------------
__global__ void build_wcat(const float* __restrict__ Wz, const float* __restrict__ bz,
                           const float* __restrict__ Wr, const float* __restrict__ br,
                           const float* __restrict__ Wn, const float* __restrict__ bn)
{
    int idx = blockIdx.x * blockDim.x + threadIdx.x;
    if (idx >= 1536 * D) return;
    int j = idx / D, k = idx % D;
    int g = j >> 9, jr = j & 511;
    const float* W = (g == 0) ? Wz : (g == 1) ? Wr : Wn;
    g_Wcat[idx] = W[jr * D + k];
    if (k == 0) {
        const float* bvec = (g == 0) ? bz : (g == 1) ? br : bn;
        g_bcat[j] = bvec[jr];
    }
}

__global__ void zero2(float* a, float* b, int n)
{
    int i = blockIdx.x * blockDim.x + threadIdx.x;
    if (i < n) { a[i] = 0.f; b[i] = 0.f; }
}

// ---------------------------------------------------------------------------
// Recurrent split-K dot kernel. Output space: nmats*512 columns x 64 rows.
//  mat 0: partial of h_u @ U        (B read k-major: U[k*512+j])
//  mat m>=1: partial of h_x @ W^T   (B read j-major: W[j*512+k])
// grid = (nmats*8, 4): blockIdx.x -> 64-wide j tile, blockIdx.y -> 128-wide K chunk
// 256 threads, 4x4 microtile over a 64x64 tile.
// ---------------------------------------------------------------------------
__global__ __launch_bounds__(256) void rec_dots(
    const float* __restrict__ Au,   // A for mat 0 (the @U dot)
    const float* __restrict__ Ax,   // A for mats 1..3 (the @W^T dots)
    const float* __restrict__ Umat,
    const float* __restrict__ Wz, const float* __restrict__ Wr,
    const float* __restrict__ Wn,
    float* __restrict__ part)
{
    const int jt = blockIdx.x;
    const int kc = blockIdx.y;
    const int mat = jt >> 3;
    const int j0  = (jt & 7) * 64;
    const int k0base = kc * 128;

    const float* A = (mat == 0) ? Au : Ax;
    const float* Bm = (mat == 0) ? Umat : (mat == 1) ? Wz : (mat == 2) ? Wr : Wn;
    const bool kmaj = (mat == 0);

    __shared__ __align__(16) float As[16][64];
    __shared__ __align__(16) float Bs[16][64];

    const int tid = threadIdx.x;
    const int tr = tid >> 4, tc = tid & 15;
    const int ar = tid >> 2, ac = (tid & 3) * 4;
    const int kr = tid >> 4, jc = (tid & 15) * 4;

    float acc[4][4];
#pragma unroll
    for (int i = 0; i < 4; i++)
#pragma unroll
        for (int j = 0; j < 4; j++) acc[i][j] = 0.f;

    for (int kt = 0; kt < 8; kt++) {
        int k0 = k0base + kt * 16;
        float4 av = *(const float4*)(A + ar * D + k0 + ac);
        As[ac + 0][ar] = av.x; As[ac + 1][ar] = av.y;
        As[ac + 2][ar] = av.z; As[ac + 3][ar] = av.w;
        if (kmaj) {
            float4 bv = *(const float4*)(Bm + (size_t)(k0 + kr) * D + j0 + jc);
            *(float4*)&Bs[kr][jc] = bv;
        } else {
            float4 bv = *(const float4*)(Bm + (size_t)(j0 + ar) * D + k0 + ac);
            Bs[ac + 0][ar] = bv.x; Bs[ac + 1][ar] = bv.y;
            Bs[ac + 2][ar] = bv.z; Bs[ac + 3][ar] = bv.w;
        }
        __syncthreads();
#pragma unroll
        for (int k = 0; k < 16; k++) {
            float a4[4], b4[4];
            *(float4*)a4 = *(const float4*)&As[k][tr * 4];
            *(float4*)b4 = *(const float4*)&Bs[k][tc * 4];
#pragma unroll
            for (int i = 0; i < 4; i++)
#pragma unroll
                for (int j = 0; j < 4; j++)
                    acc[i][j] += a4[i] * b4[j];
        }
        __syncthreads();
    }

    float* P = part + (size_t)(mat * 4 + kc) * S;
#pragma unroll
    for (int i = 0; i < 4; i++) {
        int b = tr * 4 + i;
        float4 v; v.x = acc[i][0]; v.y = acc[i][1]; v.z = acc[i][2]; v.w = acc[i][3];
        *(float4*)&P[b * D + j0 + tc * 4] = v;
    }
}

// ---------------------------------------------------------------------------
// Gate combine for cells with precomputed x-gates (encoder cell1, decoder cell)
// hW = sum of 4 K-chunk partials (mat 0). extra: optional copy of hnew (h_all)
// ---------------------------------------------------------------------------
__global__ void combine_gates(const float* __restrict__ G, int t,
                              const float* __restrict__ hold,
                              float* __restrict__ hnew,
                              const float* __restrict__ part,
                              float* __restrict__ extra)
{
    int b = blockIdx.x, j = threadIdx.x;
    int idx = b * D + j;
    float hW = part[idx] + part[S + idx] + part[2 * S + idx] + part[3 * S + idx];
    const float* g = G + (size_t)(t * BB + b) * 1536;
    float z = 1.f / (1.f + expf(-(g[j] + hW)));
    float r = 1.f / (1.f + expf(-(g[512 + j] + hW)));
    float n = tanhf(g[1024 + j] + r * hW);
    float h = hold[idx];
    float hn = (1.f - z) * h + z * n;
    hnew[idx] = hn;
    if (extra) extra[idx] = hn;
}

// Encoder cell2: x = h1new went through Wz/Wr/Wn (mats 1..3), h2 through U (mat 0)
__global__ void combine_cell2(const float* __restrict__ bz, const float* __restrict__ br,
                              const float* __restrict__ bn,
                              const float* __restrict__ hold,
                              float* __restrict__ hnew,
                              const float* __restrict__ part,
                              float* __restrict__ Hout)
{
    int b = blockIdx.x, j = threadIdx.x;
    int idx = b * D + j;
    float dU = 0.f, az = 0.f, ar = 0.f, an = 0.f;
#pragma unroll
    for (int kc = 0; kc < 4; kc++) {
        dU += part[(0 * 4 + kc) * S + idx];
        az += part[(1 * 4 + kc) * S + idx];
        ar += part[(2 * 4 + kc) * S + idx];
        an += part[(3 * 4 + kc) * S + idx];
    }
    float z = 1.f / (1.f + expf(-(az + bz[j] + dU)));
    float r = 1.f / (1.f + expf(-(ar + br[j] + dU)));
    float n = tanhf(an + bn[j] + r * dU);
    float h = hold[idx];
    float hn = (1.f - z) * h + z * n;
    hnew[idx] = hn;
    Hout[idx] = hn;
}

// ---------------------------------------------------------------------------
// Attention for one decoder step. One block per batch row.
// scores[t'] = (H[t',b,:] . h[b,:]) * scale, masked where src==PAD, softmax,
// ctx[b,:] = sum_t' alpha[t'] * H[t',b,:]
// ---------------------------------------------------------------------------
__global__ __launch_bounds__(256) void attn_kernel(
    const float* __restrict__ h, const float* __restrict__ H,
    const int* __restrict__ src, float* __restrict__ ctx_out)
{
    int b = blockIdx.x;
    int tid = threadIdx.x;
    __shared__ float hs[D];
    __shared__ float sc[TSRC];
    __shared__ float al[TSRC];

    for (int i = tid; i < D; i += 256) hs[i] = h[b * D + i];
    __syncthreads();

    int w = tid >> 5, lane = tid & 31;
    for (int tt = w; tt < TSRC; tt += 8) {
        const float* Hr = H + (size_t)tt * S + b * D;
        float s = 0.f;
        for (int kk = lane; kk < D; kk += 32) s += hs[kk] * Hr[kk];
#pragma unroll
        for (int off = 16; off; off >>= 1) s += __shfl_down_sync(0xffffffffu, s, off);
        if (lane == 0) {
            if (src[tt * BB + b] == 0) s = -1e9f;
            else s *= 0.044194173824159216f;   // 1/sqrt(512)
            sc[tt] = s;
        }
    }
    __syncthreads();
    if (tid == 0) {
        float m = -1e30f;
        for (int i = 0; i < TSRC; i++) m = fmaxf(m, sc[i]);
        float ssum = 0.f;
        for (int i = 0; i < TSRC; i++) { float e = expf(sc[i] - m); al[i] = e; ssum += e; }
        float inv = 1.f / ssum;
        for (int i = 0; i < TSRC; i++) al[i] *= inv;
    }
    __syncthreads();
    for (int j = tid; j < D; j += 256) {
        float c = 0.f;
        for (int tt = 0; tt < TSRC; tt++) c += al[tt] * H[(size_t)tt * S + b * D + j];
        ctx_out[b * D + j] = c;
    }
}

// ---------------------------------------------------------------------------
extern "C" void kernel_launch(void* const* d_in, const int* in_sizes, int n_in,
                              void* d_out, int out_size)
{
    const int*   src  = (const int*)d_in[0];
    const int*   tgt  = (const int*)d_in[1];
    const float* U    = (const float*)d_in[2];
    const float* Wz   = (const float*)d_in[3];
    const float* bz   = (const float*)d_in[4];
    const float* Wr   = (const float*)d_in[5];
    const float* br   = (const float*)d_in[6];
    const float* Wn   = (const float*)d_in[7];
    const float* bn   = (const float*)d_in[8];
    const float* Een  = (const float*)d_in[9];
    const float* Ede  = (const float*)d_in[10];
    const float* Wout = (const float*)d_in[11];
    const float* Wctx = (const float*)d_in[12];
    float* out = (float*)d_out;

    float *pWcat, *pbcat, *pGenc, *pGdec, *ph1, *ph2, *pH, *phall, *pctx, *pout, *ppart;
    cudaGetSymbolAddress((void**)&pWcat, g_Wcat);
    cudaGetSymbolAddress((void**)&pbcat, g_bcat);
    cudaGetSymbolAddress((void**)&pGenc, g_Genc);
    cudaGetSymbolAddress((void**)&pGdec, g_Gdec);
    cudaGetSymbolAddress((void**)&ph1,   g_h1);
    cudaGetSymbolAddress((void**)&ph2,   g_h2);
    cudaGetSymbolAddress((void**)&pH,    g_H);
    cudaGetSymbolAddress((void**)&phall, g_hall);
    cudaGetSymbolAddress((void**)&pctx,  g_ctx);
    cudaGetSymbolAddress((void**)&pout,  g_out);
    cudaGetSymbolAddress((void**)&ppart, g_part);

    // 1. concat gate weights, precompute x-gates (parallel over all timesteps)
    build_wcat<<<(1536 * D + 255) / 256, 256>>>(Wz, bz, Wr, br, Wn, bn);
    sgemm_nt<<<dim3(12, 24), 256>>>(nullptr, src, Een, pWcat, pbcat, nullptr,
                                    pGenc, M3, 1536, D);
    sgemm_nt<<<dim3(12, 24), 256>>>(nullptr, tgt, Ede, pWcat, pbcat, nullptr,
                                    pGdec, M3, 1536, D);
    zero2<<<(S + 255) / 256, 256>>>(ph1, ph2, S);

    // 2. encoder recurrence (sequential)
    for (int t = 0; t < TSRC; t++) {
        int cur = t & 1, nxt = cur ^ 1;
        // cell1: hW = h1@U (mat 0 only)
        rec_dots<<<dim3(8, 4), 256>>>(ph1 + cur * S, nullptr, U, Wz, Wr, Wn, ppart);
        combine_gates<<<BB, D>>>(pGenc, t, ph1 + cur * S, ph1 + nxt * S, ppart, nullptr);
        // cell2: h2@U + h1new@{Wz,Wr,Wn}
        rec_dots<<<dim3(32, 4), 256>>>(ph2 + cur * S, ph1 + nxt * S, U, Wz, Wr, Wn, ppart);
        combine_cell2<<<BB, D>>>(bz, br, bn, ph2 + cur * S, ph2 + nxt * S, ppart,
                                 pH + (size_t)t * S);
    }

    // 3. decoder recurrence + attention (sequential); h continues in g_h2 (parity 0)
    for (int t = 0; t < TTGT; t++) {
        int cur = t & 1, nxt = cur ^ 1;
        rec_dots<<<dim3(8, 4), 256>>>(ph2 + cur * S, nullptr, U, Wz, Wr, Wn, ppart);
        combine_gates<<<BB, D>>>(pGdec, t, ph2 + cur * S, ph2 + nxt * S, ppart,
                                 phall + (size_t)t * S);
        attn_kernel<<<BB, 256>>>(ph2 + nxt * S, pH, src, pctx + (size_t)t * S);
    }

    // 4. deferred output projection + big logits GEMM (parallel over all steps)
    sgemm_nt<<<dim3(4, 24), 256>>>(pctx, nullptr, nullptr, Wctx, nullptr, phall,
                                   pout, M3, D, D);
    sgemm_nt<<<dim3(250, 24), 256>>>(pout, nullptr, nullptr, Wout, nullptr, nullptr,
                                     out, M3, VDE, D);
}

// round 3
// speedup vs baseline: 1.6796x; 1.6796x over previous
#include <cuda_runtime.h>
#include <math.h>

// Problem constants
#define D    512
#define BB   64
#define TSRC 48
#define TTGT 48
#define VDE  32000
#define S    (BB * D)        // 32768 = one (B,D) state
#define M3   (TSRC * BB)     // 3072 rows

// ---------------- scratch (device globals; no allocation allowed) ------------
__device__ float g_Wcat[1536 * D];       // [Wz;Wr;Wn] rows, NT layout
__device__ float g_bcat[1536];
__device__ float g_Genc[M3 * 1536];      // precomputed x-gates (encoder layer1)
__device__ float g_Gdec[M3 * 1536];      // precomputed x-gates (decoder)
__device__ float g_h1[2 * S];            // encoder layer1 state (double buffer)
__device__ float g_h2[2 * S];            // encoder layer2 / decoder state
__device__ float g_H[TSRC * S];          // encoder outputs per step [t][b][d]
__device__ float g_hall[TTGT * S];       // decoder h per step
__device__ float g_ctx[TTGT * S];        // attention context per step
__device__ float g_out[TTGT * S];        // h + ctx@Wctx^T
__device__ float g_part[16 * S];         // split-K partials [mat*4+kc][b][d]

// ---------------------------------------------------------------------------
// tf32 tensor-core NT GEMM: C[i,j] = sum_k A[i,k]*B[j,k] (+bias[j]) (+addend)
// Optional row gather on A: row i -> E + ids[i]*K.
// BM=BN=128, BK=32, 256 threads (8 warps in 2x4), warp tile 64x32,
// mma.sync.m16n8k8 tf32. Smem row stride 36 -> bank = (4r+c)&31, conflict-free.
// Requires M%128==0, N%128==0, K%32==0 (true for all call sites).
// ---------------------------------------------------------------------------
__device__ __forceinline__ unsigned f2tf32(float x) {
    unsigned r;
    asm("cvt.rna.tf32.f32 %0, %1;" : "=r"(r) : "f"(x));
    return r;
}

__global__ __launch_bounds__(256) void sgemm_tf32(
    const float* __restrict__ A, const int* __restrict__ ids,
    const float* __restrict__ E, const float* __restrict__ Bm,
    const float* __restrict__ bias, const float* __restrict__ addend,
    float* __restrict__ C, int M, int N, int K)
{
    __shared__ unsigned As[128 * 36];
    __shared__ unsigned Bs[128 * 36];

    const int tid  = threadIdx.x;
    const int lane = tid & 31;
    const int warp = tid >> 5;
    const int row0 = blockIdx.y * 128;
    const int col0 = blockIdx.x * 128;

    const int mwarp = (warp >> 2) * 64;   // 0 or 64
    const int nwarp = (warp & 3) * 32;    // 0,32,64,96
    const int gid = lane >> 2;            // 0..7
    const int tig = lane & 3;             // 0..3

    // global load mapping: 256 threads cover 128 rows x 32 cols (float4 each)
    const int lr = tid >> 3;              // 0..31
    const int lc = (tid & 7) * 4;         // 0..28

    const float* aPtr[4];
    const float* bPtr[4];
#pragma unroll
    for (int i = 0; i < 4; i++) {
        int r = row0 + lr + 32 * i;
        aPtr[i] = ids ? (E + (size_t)ids[r] * K) : (A + (size_t)r * K);
        bPtr[i] = Bm + (size_t)(col0 + lr + 32 * i) * K;
    }

    float acc[4][4][4];
#pragma unroll
    for (int mt = 0; mt < 4; mt++)
#pragma unroll
        for (int nt = 0; nt < 4; nt++)
#pragma unroll
            for (int q = 0; q < 4; q++) acc[mt][nt][q] = 0.f;

    const int kchunks = K >> 5;   // K/32
    float4 aReg[4], bReg[4];
#pragma unroll
    for (int i = 0; i < 4; i++) {
        aReg[i] = *(const float4*)(aPtr[i] + lc);
        bReg[i] = *(const float4*)(bPtr[i] + lc);
    }

    for (int ch = 0; ch < kchunks; ch++) {
        // store current chunk to smem (tf32-converted), 16B-aligned vector stores
#pragma unroll
        for (int i = 0; i < 4; i++) {
            int base = (lr + 32 * i) * 36 + lc;
            uint4 av, bv;
            av.x = f2tf32(aReg[i].x); av.y = f2tf32(aReg[i].y);
            av.z = f2tf32(aReg[i].z); av.w = f2tf32(aReg[i].w);
            bv.x = f2tf32(bReg[i].x); bv.y = f2tf32(bReg[i].y);
            bv.z = f2tf32(bReg[i].z); bv.w = f2tf32(bReg[i].w);
            *(uint4*)&As[base] = av;
            *(uint4*)&Bs[base] = bv;
        }
        __syncthreads();

        // prefetch next chunk
        if (ch + 1 < kchunks) {
            int koff = (ch + 1) * 32 + lc;
#pragma unroll
            for (int i = 0; i < 4; i++) {
                aReg[i] = *(const float4*)(aPtr[i] + koff);
                bReg[i] = *(const float4*)(bPtr[i] + koff);
            }
        }

        // compute 4 k8 steps
#pragma unroll
        for (int ks = 0; ks < 4; ks++) {
            int k0 = ks * 8;
            unsigned bf[4][2];
#pragma unroll
            for (int nt = 0; nt < 4; nt++) {
                int nb = nwarp + nt * 8 + gid;
                bf[nt][0] = Bs[nb * 36 + k0 + tig];
                bf[nt][1] = Bs[nb * 36 + k0 + tig + 4];
            }
#pragma unroll
            for (int mt = 0; mt < 4; mt++) {
                int rm = mwarp + mt * 16 + gid;
                unsigned a0 = As[rm * 36 + k0 + tig];
                unsigned a1 = As[(rm + 8) * 36 + k0 + tig];
                unsigned a2 = As[rm * 36 + k0 + tig + 4];
                unsigned a3 = As[(rm + 8) * 36 + k0 + tig + 4];
#pragma unroll
                for (int nt = 0; nt < 4; nt++) {
                    asm volatile(
                        "mma.sync.aligned.m16n8k8.row.col.f32.tf32.tf32.f32 "
                        "{%0,%1,%2,%3}, {%4,%5,%6,%7}, {%8,%9}, {%0,%1,%2,%3};"
                        : "+f"(acc[mt][nt][0]), "+f"(acc[mt][nt][1]),
                          "+f"(acc[mt][nt][2]), "+f"(acc[mt][nt][3])
                        : "r"(a0), "r"(a1), "r"(a2), "r"(a3),
                          "r"(bf[nt][0]), "r"(bf[nt][1]));
                }
            }
        }
        __syncthreads();
    }

    // writeback
#pragma unroll
    for (int mt = 0; mt < 4; mt++) {
        int r = row0 + mwarp + mt * 16 + gid;
#pragma unroll
        for (int nt = 0; nt < 4; nt++) {
            int c = col0 + nwarp + nt * 8 + tig * 2;
            float v0 = acc[mt][nt][0], v1 = acc[mt][nt][1];
            float v2 = acc[mt][nt][2], v3 = acc[mt][nt][3];
            if (bias) {
                float b0 = bias[c], b1 = bias[c + 1];
                v0 += b0; v1 += b1; v2 += b0; v3 += b1;
            }
            if (addend) {
                float2 a0 = *(const float2*)&addend[(size_t)r * N + c];
                float2 a1 = *(const float2*)&addend[(size_t)(r + 8) * N + c];
                v0 += a0.x; v1 += a0.y; v2 += a1.x; v3 += a1.y;
            }
            float2 o0; o0.x = v0; o0.y = v1;
            float2 o1; o1.x = v2; o1.y = v3;
            *(float2*)&C[(size_t)r * N + c] = o0;
            *(float2*)&C[(size_t)(r + 8) * N + c] = o1;
        }
    }
}

// ---------------------------------------------------------------------------
// Build concatenated gate weights [Wz;Wr;Wn] (1536 x 512) + bias vector.
// ---------------------------------------------------------------------------
__global__ void build_wcat(const float* __restrict__ Wz, const float* __restrict__ bz,
                           const float* __restrict__ Wr, const float* __restrict__ br,
                           const float* __restrict__ Wn, const float* __restrict__ bn)
{
    int idx = blockIdx.x * blockDim.x + threadIdx.x;
    if (idx >= 1536 * D) return;
    int j = idx / D, k = idx % D;
    int g = j >> 9, jr = j & 511;
    const float* W = (g == 0) ? Wz : (g == 1) ? Wr : Wn;
    g_Wcat[idx] = W[jr * D + k];
    if (k == 0) {
        const float* bvec = (g == 0) ? bz : (g == 1) ? br : bn;
        g_bcat[j] = bvec[jr];
    }
}

__global__ void zero2(float* a, float* b, int n)
{
    int i = blockIdx.x * blockDim.x + threadIdx.x;
    if (i < n) { a[i] = 0.f; b[i] = 0.f; }
}

// ---------------------------------------------------------------------------
// Recurrent split-K dot kernel (fp32, latency-bound sequential path).
//  mat 0: partial of h_u @ U        (B read k-major: U[k*512+j])
//  mat m>=1: partial of h_x @ W^T   (B read j-major: W[j*512+k])
// ---------------------------------------------------------------------------
__global__ __launch_bounds__(256) void rec_dots(
    const float* __restrict__ Au,
    const float* __restrict__ Ax,
    const float* __restrict__ Umat,
    const float* __restrict__ Wz, const float* __restrict__ Wr,
    const float* __restrict__ Wn,
    float* __restrict__ part)
{
    const int jt = blockIdx.x;
    const int kc = blockIdx.y;
    const int mat = jt >> 3;
    const int j0  = (jt & 7) * 64;
    const int k0base = kc * 128;

    const float* A = (mat == 0) ? Au : Ax;
    const float* Bm = (mat == 0) ? Umat : (mat == 1) ? Wz : (mat == 2) ? Wr : Wn;
    const bool kmaj = (mat == 0);

    __shared__ __align__(16) float As[16][64];
    __shared__ __align__(16) float Bs[16][64];

    const int tid = threadIdx.x;
    const int tr = tid >> 4, tc = tid & 15;
    const int ar = tid >> 2, ac = (tid & 3) * 4;
    const int kr = tid >> 4, jc = (tid & 15) * 4;

    float acc[4][4];
#pragma unroll
    for (int i = 0; i < 4; i++)
#pragma unroll
        for (int j = 0; j < 4; j++) acc[i][j] = 0.f;

    for (int kt = 0; kt < 8; kt++) {
        int k0 = k0base + kt * 16;
        float4 av = *(const float4*)(A + ar * D + k0 + ac);
        As[ac + 0][ar] = av.x; As[ac + 1][ar] = av.y;
        As[ac + 2][ar] = av.z; As[ac + 3][ar] = av.w;
        if (kmaj) {
            float4 bv = *(const float4*)(Bm + (size_t)(k0 + kr) * D + j0 + jc);
            *(float4*)&Bs[kr][jc] = bv;
        } else {
            float4 bv = *(const float4*)(Bm + (size_t)(j0 + ar) * D + k0 + ac);
            Bs[ac + 0][ar] = bv.x; Bs[ac + 1][ar] = bv.y;
            Bs[ac + 2][ar] = bv.z; Bs[ac + 3][ar] = bv.w;
        }
        __syncthreads();
#pragma unroll
        for (int k = 0; k < 16; k++) {
            float a4[4], b4[4];
            *(float4*)a4 = *(const float4*)&As[k][tr * 4];
            *(float4*)b4 = *(const float4*)&Bs[k][tc * 4];
#pragma unroll
            for (int i = 0; i < 4; i++)
#pragma unroll
                for (int j = 0; j < 4; j++)
                    acc[i][j] += a4[i] * b4[j];
        }
        __syncthreads();
    }

    float* P = part + (size_t)(mat * 4 + kc) * S;
#pragma unroll
    for (int i = 0; i < 4; i++) {
        int b = tr * 4 + i;
        float4 v; v.x = acc[i][0]; v.y = acc[i][1]; v.z = acc[i][2]; v.w = acc[i][3];
        *(float4*)&P[b * D + j0 + tc * 4] = v;
    }
}

// ---------------------------------------------------------------------------
__global__ void combine_gates(const float* __restrict__ G, int t,
                              const float* __restrict__ hold,
                              float* __restrict__ hnew,
                              const float* __restrict__ part,
                              float* __restrict__ extra)
{
    int b = blockIdx.x, j = threadIdx.x;
    int idx = b * D + j;
    float hW = part[idx] + part[S + idx] + part[2 * S + idx] + part[3 * S + idx];
    const float* g = G + (size_t)(t * BB + b) * 1536;
    float z = 1.f / (1.f + expf(-(g[j] + hW)));
    float r = 1.f / (1.f + expf(-(g[512 + j] + hW)));
    float n = tanhf(g[1024 + j] + r * hW);
    float h = hold[idx];
    float hn = (1.f - z) * h + z * n;
    hnew[idx] = hn;
    if (extra) extra[idx] = hn;
}

__global__ void combine_cell2(const float* __restrict__ bz, const float* __restrict__ br,
                              const float* __restrict__ bn,
                              const float* __restrict__ hold,
                              float* __restrict__ hnew,
                              const float* __restrict__ part,
                              float* __restrict__ Hout)
{
    int b = blockIdx.x, j = threadIdx.x;
    int idx = b * D + j;
    float dU = 0.f, az = 0.f, ar = 0.f, an = 0.f;
#pragma unroll
    for (int kc = 0; kc < 4; kc++) {
        dU += part[(0 * 4 + kc) * S + idx];
        az += part[(1 * 4 + kc) * S + idx];
        ar += part[(2 * 4 + kc) * S + idx];
        an += part[(3 * 4 + kc) * S + idx];
    }
    float z = 1.f / (1.f + expf(-(az + bz[j] + dU)));
    float r = 1.f / (1.f + expf(-(ar + br[j] + dU)));
    float n = tanhf(an + bn[j] + r * dU);
    float h = hold[idx];
    float hn = (1.f - z) * h + z * n;
    hnew[idx] = hn;
    Hout[idx] = hn;
}

// ---------------------------------------------------------------------------
__global__ __launch_bounds__(256) void attn_kernel(
    const float* __restrict__ h, const float* __restrict__ H,
    const int* __restrict__ src, float* __restrict__ ctx_out)
{
    int b = blockIdx.x;
    int tid = threadIdx.x;
    __shared__ float hs[D];
    __shared__ float sc[TSRC];
    __shared__ float al[TSRC];

    for (int i = tid; i < D; i += 256) hs[i] = h[b * D + i];
    __syncthreads();

    int w = tid >> 5, lane = tid & 31;
    for (int tt = w; tt < TSRC; tt += 8) {
        const float* Hr = H + (size_t)tt * S + b * D;
        float s = 0.f;
        for (int kk = lane; kk < D; kk += 32) s += hs[kk] * Hr[kk];
#pragma unroll
        for (int off = 16; off; off >>= 1) s += __shfl_down_sync(0xffffffffu, s, off);
        if (lane == 0) {
            if (src[tt * BB + b] == 0) s = -1e9f;
            else s *= 0.044194173824159216f;   // 1/sqrt(512)
            sc[tt] = s;
        }
    }
    __syncthreads();
    if (tid == 0) {
        float m = -1e30f;
        for (int i = 0; i < TSRC; i++) m = fmaxf(m, sc[i]);
        float ssum = 0.f;
        for (int i = 0; i < TSRC; i++) { float e = expf(sc[i] - m); al[i] = e; ssum += e; }
        float inv = 1.f / ssum;
        for (int i = 0; i < TSRC; i++) al[i] *= inv;
    }
    __syncthreads();
    for (int j = tid; j < D; j += 256) {
        float c = 0.f;
        for (int tt = 0; tt < TSRC; tt++) c += al[tt] * H[(size_t)tt * S + b * D + j];
        ctx_out[b * D + j] = c;
    }
}

// ---------------------------------------------------------------------------
extern "C" void kernel_launch(void* const* d_in, const int* in_sizes, int n_in,
                              void* d_out, int out_size)
{
    const int*   src  = (const int*)d_in[0];
    const int*   tgt  = (const int*)d_in[1];
    const float* U    = (const float*)d_in[2];
    const float* Wz   = (const float*)d_in[3];
    const float* bz   = (const float*)d_in[4];
    const float* Wr   = (const float*)d_in[5];
    const float* br   = (const float*)d_in[6];
    const float* Wn   = (const float*)d_in[7];
    const float* bn   = (const float*)d_in[8];
    const float* Een  = (const float*)d_in[9];
    const float* Ede  = (const float*)d_in[10];
    const float* Wout = (const float*)d_in[11];
    const float* Wctx = (const float*)d_in[12];
    float* out = (float*)d_out;

    float *pWcat, *pbcat, *pGenc, *pGdec, *ph1, *ph2, *pH, *phall, *pctx, *pout, *ppart;
    cudaGetSymbolAddress((void**)&pWcat, g_Wcat);
    cudaGetSymbolAddress((void**)&pbcat, g_bcat);
    cudaGetSymbolAddress((void**)&pGenc, g_Genc);
    cudaGetSymbolAddress((void**)&pGdec, g_Gdec);
    cudaGetSymbolAddress((void**)&ph1,   g_h1);
    cudaGetSymbolAddress((void**)&ph2,   g_h2);
    cudaGetSymbolAddress((void**)&pH,    g_H);
    cudaGetSymbolAddress((void**)&phall, g_hall);
    cudaGetSymbolAddress((void**)&pctx,  g_ctx);
    cudaGetSymbolAddress((void**)&pout,  g_out);
    cudaGetSymbolAddress((void**)&ppart, g_part);

    // 1. concat gate weights, precompute x-gates (tf32 tensor cores)
    build_wcat<<<(1536 * D + 255) / 256, 256>>>(Wz, bz, Wr, br, Wn, bn);
    sgemm_tf32<<<dim3(12, 24), 256>>>(nullptr, src, Een, pWcat, pbcat, nullptr,
                                      pGenc, M3, 1536, D);
    sgemm_tf32<<<dim3(12, 24), 256>>>(nullptr, tgt, Ede, pWcat, pbcat, nullptr,
                                      pGdec, M3, 1536, D);
    zero2<<<(S + 255) / 256, 256>>>(ph1, ph2, S);

    // 2. encoder recurrence (sequential, fp32)
    for (int t = 0; t < TSRC; t++) {
        int cur = t & 1, nxt = cur ^ 1;
        rec_dots<<<dim3(8, 4), 256>>>(ph1 + cur * S, nullptr, U, Wz, Wr, Wn, ppart);
        combine_gates<<<BB, D>>>(pGenc, t, ph1 + cur * S, ph1 + nxt * S, ppart, nullptr);
        rec_dots<<<dim3(32, 4), 256>>>(ph2 + cur * S, ph1 + nxt * S, U, Wz, Wr, Wn, ppart);
        combine_cell2<<<BB, D>>>(bz, br, bn, ph2 + cur * S, ph2 + nxt * S, ppart,
                                 pH + (size_t)t * S);
    }

    // 3. decoder recurrence + attention (sequential, fp32)
    for (int t = 0; t < TTGT; t++) {
        int cur = t & 1, nxt = cur ^ 1;
        rec_dots<<<dim3(8, 4), 256>>>(ph2 + cur * S, nullptr, U, Wz, Wr, Wn, ppart);
        combine_gates<<<BB, D>>>(pGdec, t, ph2 + cur * S, ph2 + nxt * S, ppart,
                                 phall + (size_t)t * S);
        attn_kernel<<<BB, 256>>>(ph2 + nxt * S, pH, src, pctx + (size_t)t * S);
    }

    // 4. deferred output projection + big logits GEMM (tf32 tensor cores)
    sgemm_tf32<<<dim3(4, 24), 256>>>(pctx, nullptr, nullptr, Wctx, nullptr, phall,
                                     pout, M3, D, D);
    sgemm_tf32<<<dim3(250, 24), 256>>>(pout, nullptr, nullptr, Wout, nullptr, nullptr,
                                       out, M3, VDE, D);
}